// round 7
// baseline (speedup 1.0000x reference)
#include <cuda_runtime.h>
#include <math.h>

#define PI_D 3.141592653589793238462643383279502884

// ---------------- constant / scratch device globals ----------------
__device__ double g_lg[64];
__device__ double g_wq[128];
__device__ float2 g_tw128[128];
__device__ float2 g_e40f[40];

__device__ float  g_ws2 [210*128];
__device__ float  g_dinv[40*5530];
__device__ float2 g_y   [400*512];
__device__ float2 g_xf  [20*128*256];
__device__ float2 g_xl  [210*256];
__device__ float2 g_zl  [5530*512];

__device__ const int c_T[21] = {0,1,7,22,50,95,161,252,372,525,715,946,1222,1547,
                                1925,2360,2856,3417,4047,4750,5530};

__device__ double dpow_int(double x, int e) { double r = 1.0; for (int i = 0; i < e; i++) r *= x; return r; }

__device__ double wig_pow(int l, int m, int n, double cb, double sb) {
    int s0 = max(0, n - m), s1 = min(l + n, l - m);
    if (s1 < s0) return 0.0;
    double pref = 0.5 * (g_lg[l+m] + g_lg[l-m] + g_lg[l+n] + g_lg[l-n]);
    double C = exp(pref - (g_lg[l+n-s0] + g_lg[s0] + g_lg[m-n+s0] + g_lg[l-m-s0]));
    double sg = ((m - n + s0) & 1) ? -1.0 : 1.0;
    int A = 2*l + n - m - 2*s0, B = m - n + 2*s0;
    double cbA = dpow_int(cb, A), sbB = dpow_int(sb, B);
    double ci = 1.0 / (cb * cb), s2 = sb * sb;
    double val = 0.0;
    for (int s = s0; s <= s1; s++) {
        val += sg * C * cbA * sbB;
        C  *= (double)((l + n - s) * (l - m - s)) / (double)((s + 1) * (m - n + s + 1));
        sg = -sg; cbA *= ci; sbB *= s2;
    }
    return val;
}

// ---------------- setup kernels ----------------
__global__ void k_init() {
    int t = threadIdx.x;  // 128
    if (t == 0) {
        double a = 0.0; g_lg[0] = 0.0;
        for (int k = 1; k < 64; k++) { a += log((double)k); g_lg[k] = a; }
    }
    {
        double th = PI_D * (2*t + 1) / 256.0;
        double s = 0.0;
        for (int k = 0; k < 64; k++) s += sin((2*k + 1) * th) / (double)(2*k + 1);
        g_wq[t] = (2.0 / 64.0) * sin(th) * s;
        double ang = 2.0 * PI_D * t / 128.0;
        g_tw128[t] = make_float2((float)cos(ang), (float)(-sin(ang)));
    }
    if (t < 40) {
        double ang = 2.0 * PI_D * t / 40.0;
        g_e40f[t] = make_float2((float)cos(ang), (float)sin(ang));
    }
}

__global__ void k_sd() {
    __shared__ double scoef[3][24];
    int blk = blockIdx.x;
    int tid = threadIdx.x;
    if (blk < 210) {
        int lmh = blk;
        int l = 0; while ((l + 1) * (l + 2) / 2 <= lmh) l++;
        int m = lmh - l * (l + 1) / 2;
        int s1 = l - m;
        if (tid == 0) {
            double pref = 0.5 * (g_lg[l+m] + g_lg[l-m]) + g_lg[l];
            double C = exp(pref - (g_lg[l] + g_lg[m] + g_lg[l-m]));
            double sg = (m & 1) ? -1.0 : 1.0;
            for (int s = 0; s <= s1; s++) {
                scoef[0][s] = sg * C;
                C *= (double)((l - s) * (l - m - s)) / (double)((s + 1) * (m + s + 1));
                sg = -sg;
            }
        }
        __syncthreads();
        int j = tid;
        double th = PI_D * (2*j + 1) / 256.0;
        double cb = cos(0.5 * th), sb = sin(0.5 * th);
        double cbA = dpow_int(cb, 2*l - m), sbB = dpow_int(sb, m);
        double ci = 1.0 / (cb * cb), s2 = sb * sb;
        double val = 0.0;
        for (int s = 0; s <= s1; s++) { val += scoef[0][s] * cbA * sbB; cbA *= ci; sbB *= s2; }
        g_ws2[lmh * 128 + j] = (float)(val * g_wq[j]);
    } else {
        int t0 = (blk - 210) * 3;
        if (tid < 3 && t0 + tid < 5530) {
            int t = t0 + tid;
            int l = 0; while (c_T[l + 1] <= t) l++;
            int r = t - c_T[l];
            int m = r / (2*l + 1);
            int n = r % (2*l + 1) - l;
            int s0 = max(0, n - m), s1 = min(l + n, l - m);
            double pref = 0.5 * (g_lg[l+m] + g_lg[l-m] + g_lg[l+n] + g_lg[l-n]);
            double C = exp(pref - (g_lg[l+n-s0] + g_lg[s0] + g_lg[m-n+s0] + g_lg[l-m-s0]));
            double sg = ((m - n + s0) & 1) ? -1.0 : 1.0;
            for (int s = s0; s <= s1; s++) {
                scoef[tid][s - s0] = sg * C;
                C *= (double)((l + n - s) * (l - m - s)) / (double)((s + 1) * (m - n + s + 1));
                sg = -sg;
            }
        }
        __syncthreads();
        int sub = tid / 40, b = tid % 40;
        int t = t0 + sub;
        if (sub < 3 && t < 5530) {
            int l = 0; while (c_T[l + 1] <= t) l++;
            int r = t - c_T[l];
            int m = r / (2*l + 1);
            int n = r % (2*l + 1) - l;
            int s0 = max(0, n - m), s1 = min(l + n, l - m);
            double th = PI_D * (2*b + 1) / 80.0;
            double cb = cos(0.5 * th), sb = sin(0.5 * th);
            int A0 = 2*l + n - m - 2*s0, B0 = m - n + 2*s0;
            double cbA = dpow_int(cb, A0), sbB = dpow_int(sb, B0);
            double ci = 1.0 / (cb * cb), s2 = sb * sb;
            double val = 0.0;
            int nt = s1 - s0;
            for (int s = 0; s <= nt; s++) { val += scoef[sub][s] * cbA * sbB; cbA *= ci; sbB *= s2; }
            g_dinv[b * 5530 + t] = (float)(val * (double)(2*l + 1));
        }
    }
}

__global__ void k_y(const float* __restrict__ ker) {
    __shared__ float2 sFk[24];
    int lmf = blockIdx.x, io = threadIdx.x;                   // 400 x 512
    int l = 0; while ((l + 1) * (l + 1) <= lmf) l++;
    int m = lmf - l * l - l;
    if (io < 24) {
        double beta  = (io / 8 + 1) * (PI_D / 24.0);
        double alpha = (io % 8) * (PI_D / 4.0);
        double cb = cos(0.5 * beta), sb = sin(0.5 * beta);
        double d = wig_pow(l, m, 0, cb, sb);
        double sn, cn; sincos(-(double)m * alpha, &sn, &cn);
        sFk[io] = make_float2((float)(d * cn), (float)(d * sn));
    }
    __syncthreads();
    const float sc = 0.008164965809277261f;
    float ar = 0.f, ai = 0.f;
    #pragma unroll
    for (int p = 0; p < 24; p++) {
        float k = ker[io * 24 + p];
        ar = fmaf(k, sFk[p].x, ar);
        ai = fmaf(k, sFk[p].y, ai);
    }
    g_y[lmf * 512 + io] = make_float2(sc * ar, sc * ai);
}

// ---------------- main pipeline ----------------
__global__ void kx1(const float* __restrict__ x) {
    __shared__ float  xs[32][129];
    __shared__ float2 stw[128];
    int tid = threadIdx.x;
    int j = blockIdx.x;
    int zi0 = blockIdx.y * 32;
    if (tid < 128) stw[tid] = g_tw128[tid];
    for (int i = tid; i < 4096; i += 256) {
        int r = i >> 7, c = i & 127;
        xs[r][c] = x[((size_t)(zi0 + r) * 128 + j) * 128 + c];
    }
    __syncthreads();
    int w = tid >> 5, l = tid & 31;
    for (int m = w; m < 20; m += 8) {
        float re = 0.f, im = 0.f;
        int idx = 0;
        #pragma unroll 8
        for (int a = 0; a < 128; a++) {
            float xv = xs[l][a];
            float2 t = stw[idx];
            re = fmaf(xv, t.x, re);
            im = fmaf(xv, t.y, im);
            idx = (idx + m) & 127;
        }
        g_xf[(m * 128 + j) * 256 + zi0 + l] = make_float2(re, im);
    }
}

__global__ void kx2() {
    __shared__ float sw[128];
    int lmh = blockIdx.x, zi = threadIdx.x;
    if (zi < 128) sw[zi] = g_ws2[lmh * 128 + zi];
    __syncthreads();
    int l = 0; while ((l + 1) * (l + 2) / 2 <= lmh) l++;
    int m = lmh - l * (l + 1) / 2;
    const float2* base = g_xf + m * 128 * 256;
    float ar = 0.f, ai = 0.f;
    #pragma unroll 8
    for (int j = 0; j < 128; j++) {
        float w = sw[j];
        float2 v = base[j * 256 + zi];
        ar = fmaf(w, v.x, ar);
        ai = fmaf(w, v.y, ai);
    }
    g_xl[lmh * 256 + zi] = make_float2(ar, ai);
}

__global__ void kx3() {
    __shared__ float2 sx[256];
    __shared__ float2 sy[512];
    int t = blockIdx.x, tid = threadIdx.x;
    int l = 0; while (c_T[l + 1] <= t) l++;
    int r = t - c_T[l];
    int m = r / (2*l + 1), ni = r % (2*l + 1);
    int lmh = l * (l + 1) / 2 + m;
    int lmf = l * l + ni;
    if (tid < 256) sx[tid] = g_xl[lmh * 256 + tid];
    sy[tid] = g_y[lmf * 512 + tid];
    __syncthreads();
    int z = tid >> 5, o = tid & 31;
    float ar = 0.f, ai = 0.f;
    #pragma unroll
    for (int i = 0; i < 16; i++) {
        float2 xv = sx[z * 16 + i];
        float2 yv = sy[i * 32 + o];
        ar += xv.x * yv.x + xv.y * yv.y;
        ai += xv.y * yv.x - xv.x * yv.y;
    }
    g_zl[t * 512 + tid] = make_float2(ar, ai);
}

// fused synthesis v7: predicated full-unroll stage1 (MLP), double-buffered smem
// (2 barriers/m), smem twiddle table, b-tile=2, n- and m-parity folds.
__global__ void __launch_bounds__(320) kx4(float* __restrict__ out, const float* __restrict__ bias) {
    __shared__ float sOm[2][2][2][2][8][28];  // [buf][n-par][re/im][b][zol][k]
    __shared__ float sS [2][2][2][2][8][28];  // [buf][n-par][re/im][b][zol][gp]
    __shared__ float sTw[2][2][20][20];       // [n-par][re/im][g][k]
    __shared__ float2 se[40];
    int tid = threadIdx.x;
    int zo0 = blockIdx.x * 8;
    int b0  = blockIdx.y * 2;
    if (tid < 40) se[tid] = g_e40f[tid];
    __syncthreads();
    // twiddle table: tw[par][g][k] = e^{+i 2pi (n0+2k) g / 40}, n0 = -18 (even) / -19 (odd)
    for (int i = tid; i < 2 * 20 * 20; i += 320) {
        int par = i / 400, rem = i % 400;
        int g = rem / 20, k = rem % 20;
        int basek = par ? 21 : 22;
        float2 e = se[((basek + 2 * k) * g) % 40];
        sTw[par][0][g][k] = e.x;
        sTw[par][1][g][k] = e.y;
    }
    // zero even-parity pad slot k=19, both buffers
    if (tid < 64) {
        int buf = tid & 1, cc = (tid >> 1) & 1, bb = (tid >> 2) & 1, zz = (tid >> 3) & 7;
        sOm[buf][0][cc][bb][zz][19] = 0.f;
    }

    // roles
    int nidx = tid >> 3, zol1 = tid & 7;                    // stage 1
    int par2 = (tid >= 160) ? 1 : 0;                        // stage 2 (warp-uniform)
    int r2   = tid - 160 * par2;
    int g2   = r2 >> 3, zol2 = r2 & 7;
    int a3 = tid >> 4;                                      // stage 3
    int rem3 = tid & 15;
    int zol3 = rem3 >> 1, gh = rem3 & 1;
    float sgn = gh ? -1.f : 1.f;

    const int cT[21] = {0,1,7,22,50,95,161,252,372,525,715,946,1222,1547,
                        1925,2360,2856,3417,4047,4750,5530};

    int n1 = nidx - 19;
    int an1 = n1 < 0 ? -n1 : n1;
    int p1 = n1 & 1;
    int k1 = (n1 + 18 + p1) >> 1;

    float f0P[20], f0M[20], f1P[20], f1M[20];
    #pragma unroll
    for (int g = 0; g < 20; g++) { f0P[g] = 0.f; f0M[g] = 0.f; f1P[g] = 0.f; f1M[g] = 0.f; }
    __syncthreads();

    for (int m = 0; m < 20; m++) {
        int mb = m & 1;
        // ---- stage 1: Om[n] = sum_l dinv[b][l,m,n] * zl[l,m,n][zo] (predicated unroll, 2 b's)
        if (nidx < 39) {
            int lmin = m > an1 ? m : an1;
            float o0r = 0.f, o0i = 0.f, o1r = 0.f, o1i = 0.f;
            #pragma unroll
            for (int l = 0; l < 20; l++) {
                bool act = (l >= lmin);
                int tt = cT[l] + m * (2*l + 1) + (n1 + l);
                float d0 = act ? g_dinv[b0 * 5530 + tt] : 0.f;
                float d1 = act ? g_dinv[(b0 + 1) * 5530 + tt] : 0.f;
                float2 zv = act ? g_zl[(size_t)tt * 512 + zo0 + zol1] : make_float2(0.f, 0.f);
                o0r = fmaf(d0, zv.x, o0r);
                o0i = fmaf(d0, zv.y, o0i);
                o1r = fmaf(d1, zv.x, o1r);
                o1i = fmaf(d1, zv.y, o1i);
            }
            sOm[mb][p1][0][0][zol1][k1] = o0r;
            sOm[mb][p1][1][0][zol1][k1] = o0i;
            sOm[mb][p1][0][1][zol1][k1] = o1r;
            sOm[mb][p1][1][1][zol1][k1] = o1i;
        }
        __syncthreads();
        // ---- stage 2: S_par[g] = sum_k Om_par[k] * tw[par][g][k], 2 b's
        {
            float S0r = 0.f, S0i = 0.f, S1r = 0.f, S1i = 0.f;
            const float4* A0r = (const float4*)&sOm[mb][par2][0][0][zol2][0];
            const float4* A0i = (const float4*)&sOm[mb][par2][1][0][zol2][0];
            const float4* A1r = (const float4*)&sOm[mb][par2][0][1][zol2][0];
            const float4* A1i = (const float4*)&sOm[mb][par2][1][1][zol2][0];
            const float4* Tr  = (const float4*)&sTw[par2][0][g2][0];
            const float4* Ti  = (const float4*)&sTw[par2][1][g2][0];
            #pragma unroll
            for (int q = 0; q < 5; q++) {
                float4 ar0 = A0r[q], ai0 = A0i[q], ar1 = A1r[q], ai1 = A1i[q];
                float4 tr = Tr[q], tiv = Ti[q];
                S0r = fmaf(ar0.x, tr.x, S0r); S0r = fmaf(-ai0.x, tiv.x, S0r);
                S0i = fmaf(ar0.x, tiv.x, S0i); S0i = fmaf( ai0.x, tr.x, S0i);
                S1r = fmaf(ar1.x, tr.x, S1r); S1r = fmaf(-ai1.x, tiv.x, S1r);
                S1i = fmaf(ar1.x, tiv.x, S1i); S1i = fmaf( ai1.x, tr.x, S1i);
                S0r = fmaf(ar0.y, tr.y, S0r); S0r = fmaf(-ai0.y, tiv.y, S0r);
                S0i = fmaf(ar0.y, tiv.y, S0i); S0i = fmaf( ai0.y, tr.y, S0i);
                S1r = fmaf(ar1.y, tr.y, S1r); S1r = fmaf(-ai1.y, tiv.y, S1r);
                S1i = fmaf(ar1.y, tiv.y, S1i); S1i = fmaf( ai1.y, tr.y, S1i);
                S0r = fmaf(ar0.z, tr.z, S0r); S0r = fmaf(-ai0.z, tiv.z, S0r);
                S0i = fmaf(ar0.z, tiv.z, S0i); S0i = fmaf( ai0.z, tr.z, S0i);
                S1r = fmaf(ar1.z, tr.z, S1r); S1r = fmaf(-ai1.z, tiv.z, S1r);
                S1i = fmaf(ar1.z, tiv.z, S1i); S1i = fmaf( ai1.z, tr.z, S1i);
                S0r = fmaf(ar0.w, tr.w, S0r); S0r = fmaf(-ai0.w, tiv.w, S0r);
                S0i = fmaf(ar0.w, tiv.w, S0i); S0i = fmaf( ai0.w, tr.w, S0i);
                S1r = fmaf(ar1.w, tr.w, S1r); S1r = fmaf(-ai1.w, tiv.w, S1r);
                S1i = fmaf(ar1.w, tiv.w, S1i); S1i = fmaf( ai1.w, tr.w, S1i);
            }
            sS[mb][par2][0][0][zol2][g2] = S0r;
            sS[mb][par2][1][0][zol2][g2] = S0i;
            sS[mb][par2][0][1][zol2][g2] = S1r;
            sS[mb][par2][1][1][zol2][g2] = S1i;
        }
        __syncthreads();
        // ---- stage 3: f += w_m Re( e^{i 2pi m a/40} (Se + sgn*So) ), split by m parity
        {
            float2 e = se[(m * a3) % 40];
            float w = (m == 0) ? 1.f : 2.f;
            float wc = w * e.x, ws = w * e.y;
            const float4* Er0 = (const float4*)&sS[mb][0][0][0][zol3][0];
            const float4* Ei0 = (const float4*)&sS[mb][0][1][0][zol3][0];
            const float4* Or0 = (const float4*)&sS[mb][1][0][0][zol3][0];
            const float4* Oi0 = (const float4*)&sS[mb][1][1][0][zol3][0];
            const float4* Er1 = (const float4*)&sS[mb][0][0][1][zol3][0];
            const float4* Ei1 = (const float4*)&sS[mb][0][1][1][zol3][0];
            const float4* Or1 = (const float4*)&sS[mb][1][0][1][zol3][0];
            const float4* Oi1 = (const float4*)&sS[mb][1][1][1][zol3][0];
            if ((m & 1) == 0) {
                #pragma unroll
                for (int q = 0; q < 5; q++) {
                    float4 er = Er0[q], ei = Ei0[q], orv = Or0[q], oiv = Oi0[q];
                    f0P[4*q  ] = fmaf(wc, fmaf(sgn, orv.x, er.x), fmaf(-ws, fmaf(sgn, oiv.x, ei.x), f0P[4*q  ]));
                    f0P[4*q+1] = fmaf(wc, fmaf(sgn, orv.y, er.y), fmaf(-ws, fmaf(sgn, oiv.y, ei.y), f0P[4*q+1]));
                    f0P[4*q+2] = fmaf(wc, fmaf(sgn, orv.z, er.z), fmaf(-ws, fmaf(sgn, oiv.z, ei.z), f0P[4*q+2]));
                    f0P[4*q+3] = fmaf(wc, fmaf(sgn, orv.w, er.w), fmaf(-ws, fmaf(sgn, oiv.w, ei.w), f0P[4*q+3]));
                    er = Er1[q]; ei = Ei1[q]; orv = Or1[q]; oiv = Oi1[q];
                    f1P[4*q  ] = fmaf(wc, fmaf(sgn, orv.x, er.x), fmaf(-ws, fmaf(sgn, oiv.x, ei.x), f1P[4*q  ]));
                    f1P[4*q+1] = fmaf(wc, fmaf(sgn, orv.y, er.y), fmaf(-ws, fmaf(sgn, oiv.y, ei.y), f1P[4*q+1]));
                    f1P[4*q+2] = fmaf(wc, fmaf(sgn, orv.z, er.z), fmaf(-ws, fmaf(sgn, oiv.z, ei.z), f1P[4*q+2]));
                    f1P[4*q+3] = fmaf(wc, fmaf(sgn, orv.w, er.w), fmaf(-ws, fmaf(sgn, oiv.w, ei.w), f1P[4*q+3]));
                }
            } else {
                #pragma unroll
                for (int q = 0; q < 5; q++) {
                    float4 er = Er0[q], ei = Ei0[q], orv = Or0[q], oiv = Oi0[q];
                    f0M[4*q  ] = fmaf(wc, fmaf(sgn, orv.x, er.x), fmaf(-ws, fmaf(sgn, oiv.x, ei.x), f0M[4*q  ]));
                    f0M[4*q+1] = fmaf(wc, fmaf(sgn, orv.y, er.y), fmaf(-ws, fmaf(sgn, oiv.y, ei.y), f0M[4*q+1]));
                    f0M[4*q+2] = fmaf(wc, fmaf(sgn, orv.z, er.z), fmaf(-ws, fmaf(sgn, oiv.z, ei.z), f0M[4*q+2]));
                    f0M[4*q+3] = fmaf(wc, fmaf(sgn, orv.w, er.w), fmaf(-ws, fmaf(sgn, oiv.w, ei.w), f0M[4*q+3]));
                    er = Er1[q]; ei = Ei1[q]; orv = Or1[q]; oiv = Oi1[q];
                    f1M[4*q  ] = fmaf(wc, fmaf(sgn, orv.x, er.x), fmaf(-ws, fmaf(sgn, oiv.x, ei.x), f1M[4*q  ]));
                    f1M[4*q+1] = fmaf(wc, fmaf(sgn, orv.y, er.y), fmaf(-ws, fmaf(sgn, oiv.y, ei.y), f1M[4*q+1]));
                    f1M[4*q+2] = fmaf(wc, fmaf(sgn, orv.z, er.z), fmaf(-ws, fmaf(sgn, oiv.z, ei.z), f1M[4*q+2]));
                    f1M[4*q+3] = fmaf(wc, fmaf(sgn, orv.w, er.w), fmaf(-ws, fmaf(sgn, oiv.w, ei.w), f1M[4*q+3]));
                }
            }
        }
        // no end-of-loop barrier: next stage1 writes the OTHER buffer
    }

    // ---- write: rows a (fP+fM) and a+20 (fP-fM), columns gh*20..gh*20+19
    int zo = zo0 + zol3;
    float bv = bias[zo & 31];
    float* base0 = out + ((size_t)zo * 40 + b0) * 1600 + a3 * 40 + gh * 20;
    float4* oa0 = (float4*)base0;
    float4* ob0 = (float4*)(base0 + 800);
    float4* oa1 = (float4*)(base0 + 1600);
    float4* ob1 = (float4*)(base0 + 2400);
    #pragma unroll
    for (int q = 0; q < 5; q++) {
        oa0[q] = make_float4(f0P[4*q]   + f0M[4*q]   + bv, f0P[4*q+1] + f0M[4*q+1] + bv,
                             f0P[4*q+2] + f0M[4*q+2] + bv, f0P[4*q+3] + f0M[4*q+3] + bv);
        ob0[q] = make_float4(f0P[4*q]   - f0M[4*q]   + bv, f0P[4*q+1] - f0M[4*q+1] + bv,
                             f0P[4*q+2] - f0M[4*q+2] + bv, f0P[4*q+3] - f0M[4*q+3] + bv);
        oa1[q] = make_float4(f1P[4*q]   + f1M[4*q]   + bv, f1P[4*q+1] + f1M[4*q+1] + bv,
                             f1P[4*q+2] + f1M[4*q+2] + bv, f1P[4*q+3] + f1M[4*q+3] + bv);
        ob1[q] = make_float4(f1P[4*q]   - f1M[4*q]   + bv, f1P[4*q+1] - f1M[4*q+1] + bv,
                             f1P[4*q+2] - f1M[4*q+2] + bv, f1P[4*q+3] - f1M[4*q+3] + bv);
    }
}

// ---------------- launch ----------------
extern "C" void kernel_launch(void* const* d_in, const int* in_sizes, int n_in,
                              void* d_out, int out_size) {
    const float* x    = (const float*)d_in[0];
    const float* ker  = (const float*)d_in[1];
    const float* bias = (const float*)d_in[2];
    float* out = (float*)d_out;

    k_init<<<1, 128>>>();
    k_sd  <<<210 + 1844, 128>>>();
    k_y   <<<400, 512>>>(ker);

    kx1<<<dim3(128, 8), 256>>>(x);
    kx2<<<210, 256>>>();
    kx3<<<5530, 512>>>();
    kx4<<<dim3(64, 20), 320>>>(out, bias);
}